// round 1
// baseline (speedup 1.0000x reference)
#include <cuda_runtime.h>

#define NN 100000
#define EE 1600000
#define EPP 200000

// ---------------- scratch (static device globals; no allocation) ------------
__device__ int   g_deg[NN];
__device__ int   g_off[NN + 1];
__device__ int   g_cur[NN];
__device__ int   g_adj[EE];
__device__ float g_dinv[NN];
__device__ float g_hs1[(size_t)NN * 128];  // (x@W1) * dinv[row]
__device__ float g_a1 [(size_t)NN * 128];  // aggregated layer-1 (pre-bias/relu)
__device__ float g_hs2[(size_t)NN * 64];   // (relu(a1+b1)@W2) * dinv[row]
__device__ float g_z  [(size_t)NN * 64];   // final embeddings
__device__ int   g_bsum[256];
__device__ int   g_boff[256];

// ---------------- degree / CSR build ---------------------------------------
__global__ void k_init_deg() {
    int i = blockIdx.x * blockDim.x + threadIdx.x;
    if (i < NN) g_deg[i] = 0;
}

__global__ void k_count(const int* __restrict__ dst) {
    int e = blockIdx.x * blockDim.x + threadIdx.x;
    if (e < EE) atomicAdd(&g_deg[dst[e]], 1);
}

__global__ void k_dinv() {
    int i = blockIdx.x * blockDim.x + threadIdx.x;
    if (i < NN) g_dinv[i] = rsqrtf((float)(g_deg[i] + 1));  // +1 self loop
}

// block-level exclusive scan, 512 elems/block
__global__ void k_scan1() {
    __shared__ int s[512];
    int t = threadIdx.x;
    int idx = blockIdx.x * 512 + t;
    int v = (idx < NN) ? g_deg[idx] : 0;
    s[t] = v;
    __syncthreads();
#pragma unroll
    for (int o = 1; o < 512; o <<= 1) {
        int x = (t >= o) ? s[t - o] : 0;
        __syncthreads();
        s[t] += x;
        __syncthreads();
    }
    if (idx < NN) g_off[idx] = s[t] - v;       // exclusive within block
    if (t == 511) g_bsum[blockIdx.x] = s[511]; // block total
}

__global__ void k_scan2(int nb) {
    __shared__ int s[256];
    int t = threadIdx.x;
    int v = (t < nb) ? g_bsum[t] : 0;
    s[t] = v;
    __syncthreads();
#pragma unroll
    for (int o = 1; o < 256; o <<= 1) {
        int x = (t >= o) ? s[t - o] : 0;
        __syncthreads();
        s[t] += x;
        __syncthreads();
    }
    if (t < nb) g_boff[t] = s[t] - v;          // exclusive block offsets
}

__global__ void k_scan3() {
    int t = threadIdx.x;
    int idx = blockIdx.x * 512 + t;
    if (idx < NN) {
        int val = g_off[idx] + g_boff[blockIdx.x];
        g_off[idx] = val;
        g_cur[idx] = val;
        if (idx == 0) g_off[NN] = EE;
    }
}

__global__ void k_fill(const int* __restrict__ src, const int* __restrict__ dst) {
    int e = blockIdx.x * blockDim.x + threadIdx.x;
    if (e < EE) {
        int d = dst[e];
        int p = atomicAdd(&g_cur[d], 1);
        g_adj[p] = src[e];
    }
}

// ---------------- GEMM 1: hs1 = (x @ W1) * dinv[row] ------------------------
// block = 256 threads, tile 32 rows x 128 cols; W1 streamed through L1.
__global__ void k_gemm1(const float* __restrict__ x, const float* __restrict__ W) {
    __shared__ float Xs[32 * 128];
    int row0 = blockIdx.x * 32;
    float4* xs4 = (float4*)Xs;
    const float4* xg = (const float4*)(x + (size_t)row0 * 128);
#pragma unroll
    for (int j = 0; j < 4; j++) xs4[threadIdx.x + 256 * j] = xg[threadIdx.x + 256 * j];
    __syncthreads();

    int c4 = threadIdx.x & 31;          // float4 column index (cols c4*4..c4*4+3)
    int r0 = (threadIdx.x >> 5) * 4;    // 4 rows per thread
    float4 a0 = {0,0,0,0}, a1 = {0,0,0,0}, a2 = {0,0,0,0}, a3 = {0,0,0,0};
    const float4* W4 = (const float4*)W;
#pragma unroll 4
    for (int k = 0; k < 128; k++) {
        float4 w = W4[k * 32 + c4];
        float x0 = Xs[(r0 + 0) * 128 + k];
        float x1 = Xs[(r0 + 1) * 128 + k];
        float x2 = Xs[(r0 + 2) * 128 + k];
        float x3 = Xs[(r0 + 3) * 128 + k];
        a0.x += x0 * w.x; a0.y += x0 * w.y; a0.z += x0 * w.z; a0.w += x0 * w.w;
        a1.x += x1 * w.x; a1.y += x1 * w.y; a1.z += x1 * w.z; a1.w += x1 * w.w;
        a2.x += x2 * w.x; a2.y += x2 * w.y; a2.z += x2 * w.z; a2.w += x2 * w.w;
        a3.x += x3 * w.x; a3.y += x3 * w.y; a3.z += x3 * w.z; a3.w += x3 * w.w;
    }
    float4* out4 = (float4*)g_hs1;
    int r = row0 + r0;
    float d0 = g_dinv[r + 0], d1 = g_dinv[r + 1], d2 = g_dinv[r + 2], d3 = g_dinv[r + 3];
    float4 o;
    o.x = a0.x * d0; o.y = a0.y * d0; o.z = a0.z * d0; o.w = a0.w * d0; out4[(size_t)(r + 0) * 32 + c4] = o;
    o.x = a1.x * d1; o.y = a1.y * d1; o.z = a1.z * d1; o.w = a1.w * d1; out4[(size_t)(r + 1) * 32 + c4] = o;
    o.x = a2.x * d2; o.y = a2.y * d2; o.z = a2.z * d2; o.w = a2.w * d2; out4[(size_t)(r + 2) * 32 + c4] = o;
    o.x = a3.x * d3; o.y = a3.y * d3; o.z = a3.z * d3; o.w = a3.w * d3; out4[(size_t)(r + 3) * 32 + c4] = o;
}

// ---------------- AGG 1: a1[d] = dinv[d] * (hs1[d] + sum_in hs1[s]) ---------
// one warp per destination node; 4 floats per lane (128 dims)
__global__ void k_agg1() {
    int gw = (blockIdx.x * blockDim.x + threadIdx.x) >> 5;
    if (gw >= NN) return;
    int lane = threadIdx.x & 31;
    int o0 = g_off[gw], o1 = g_off[gw + 1];
    const float4* base = (const float4*)g_hs1;
    float4 acc = base[(size_t)gw * 32 + lane];
    for (int i = o0; i < o1; i++) {
        int s = g_adj[i];
        float4 v = base[(size_t)s * 32 + lane];
        acc.x += v.x; acc.y += v.y; acc.z += v.z; acc.w += v.w;
    }
    float dv = g_dinv[gw];
    acc.x *= dv; acc.y *= dv; acc.z *= dv; acc.w *= dv;
    ((float4*)g_a1)[(size_t)gw * 32 + lane] = acc;
}

// ---------------- GEMM 2: hs2 = (relu(a1 + b1) @ W2) * dinv[row] ------------
// block = 256 threads, tile 64 rows x 64 cols
__global__ void k_gemm2(const float* __restrict__ b1, const float* __restrict__ W2) {
    __shared__ float Xs[64][132];   // padded rows (132 floats = 528B, 16B aligned)
    int row0 = blockIdx.x * 64;
    // load tile with bias+relu applied; 2048 float4 slots, 8 per thread
#pragma unroll
    for (int j = 0; j < 8; j++) {
        int li = threadIdx.x + 256 * j;  // 0..2047
        int r  = li >> 5;
        int c4 = li & 31;
        int gr = row0 + r;
        float4 v = {0, 0, 0, 0};
        if (gr < NN) {
            float4 a = ((const float4*)g_a1)[(size_t)gr * 32 + c4];
            float4 b = ((const float4*)b1)[c4];
            v.x = fmaxf(a.x + b.x, 0.f);
            v.y = fmaxf(a.y + b.y, 0.f);
            v.z = fmaxf(a.z + b.z, 0.f);
            v.w = fmaxf(a.w + b.w, 0.f);
        }
        *((float4*)&Xs[r][c4 * 4]) = v;
    }
    __syncthreads();

    int c4 = threadIdx.x & 15;          // 16 float4-col groups -> 64 cols
    int r0 = (threadIdx.x >> 4) * 4;    // 16 row groups x 4 rows -> 64 rows
    float4 a0 = {0,0,0,0}, a1v = {0,0,0,0}, a2 = {0,0,0,0}, a3 = {0,0,0,0};
    const float4* W4 = (const float4*)W2;
#pragma unroll 4
    for (int k = 0; k < 128; k++) {
        float4 w = W4[k * 16 + c4];
        float x0 = Xs[r0 + 0][k];
        float x1 = Xs[r0 + 1][k];
        float x2 = Xs[r0 + 2][k];
        float x3 = Xs[r0 + 3][k];
        a0.x  += x0 * w.x; a0.y  += x0 * w.y; a0.z  += x0 * w.z; a0.w  += x0 * w.w;
        a1v.x += x1 * w.x; a1v.y += x1 * w.y; a1v.z += x1 * w.z; a1v.w += x1 * w.w;
        a2.x  += x2 * w.x; a2.y  += x2 * w.y; a2.z  += x2 * w.z; a2.w  += x2 * w.w;
        a3.x  += x3 * w.x; a3.y  += x3 * w.y; a3.z  += x3 * w.z; a3.w  += x3 * w.w;
    }
    float4* out4 = (float4*)g_hs2;
    int r = row0 + r0;
    float4 accs[4] = {a0, a1v, a2, a3};
#pragma unroll
    for (int j = 0; j < 4; j++) {
        int gr = r + j;
        if (gr < NN) {
            float dv = g_dinv[gr];
            float4 o;
            o.x = accs[j].x * dv; o.y = accs[j].y * dv;
            o.z = accs[j].z * dv; o.w = accs[j].w * dv;
            out4[(size_t)gr * 16 + c4] = o;
        }
    }
}

// ---------------- AGG 2: z[d] = dinv[d]*(hs2[d] + sum_in hs2[s]) + b2 -------
// one warp per node; 2 floats per lane (64 dims)
__global__ void k_agg2(const float* __restrict__ b2) {
    int gw = (blockIdx.x * blockDim.x + threadIdx.x) >> 5;
    if (gw >= NN) return;
    int lane = threadIdx.x & 31;
    int o0 = g_off[gw], o1 = g_off[gw + 1];
    const float2* base = (const float2*)g_hs2;
    float2 acc = base[(size_t)gw * 32 + lane];
    for (int i = o0; i < o1; i++) {
        int s = g_adj[i];
        float2 v = base[(size_t)s * 32 + lane];
        acc.x += v.x; acc.y += v.y;
    }
    float dv = g_dinv[gw];
    float2 b = ((const float2*)b2)[lane];
    acc.x = acc.x * dv + b.x;
    acc.y = acc.y * dv + b.y;
    ((float2*)g_z)[(size_t)gw * 32 + lane] = acc;
}

// ---------------- decode: logits[i] = dot(z[e0], z[e1]) ---------------------
// one warp per edge; 2 floats per lane + shfl reduce
__global__ void k_decode(const int* __restrict__ pos, const int* __restrict__ neg,
                         float* __restrict__ out) {
    int gw = (blockIdx.x * blockDim.x + threadIdx.x) >> 5;
    if (gw >= 2 * EPP) return;
    int lane = threadIdx.x & 31;
    int a, b;
    if (gw < EPP) { a = pos[gw];        b = pos[EPP + gw]; }
    else          { int j = gw - EPP; a = neg[j]; b = neg[EPP + j]; }
    const float2* Z = (const float2*)g_z;
    float2 za = Z[(size_t)a * 32 + lane];
    float2 zb = Z[(size_t)b * 32 + lane];
    float p = za.x * zb.x + za.y * zb.y;
#pragma unroll
    for (int o = 16; o > 0; o >>= 1) p += __shfl_xor_sync(0xFFFFFFFFu, p, o);
    if (lane == 0) out[gw] = p;
}

// ---------------- launch ----------------------------------------------------
extern "C" void kernel_launch(void* const* d_in, const int* in_sizes, int n_in,
                              void* d_out, int out_size) {
    const float* x   = (const float*)d_in[0];
    const int*   ei  = (const int*)  d_in[1];  // [2, E]
    const int*   pos = (const int*)  d_in[2];  // [2, EP]
    const int*   neg = (const int*)  d_in[3];  // [2, EP]
    const float* W1  = (const float*)d_in[4];
    const float* b1  = (const float*)d_in[5];
    const float* W2  = (const float*)d_in[6];
    const float* b2  = (const float*)d_in[7];
    float* out = (float*)d_out;

    const int* src = ei;
    const int* dst = ei + EE;

    const int nb_scan = (NN + 511) / 512;  // 196

    k_init_deg<<<(NN + 255) / 256, 256>>>();
    k_count<<<(EE + 255) / 256, 256>>>(dst);
    k_dinv<<<(NN + 255) / 256, 256>>>();
    k_scan1<<<nb_scan, 512>>>();
    k_scan2<<<1, 256>>>(nb_scan);
    k_scan3<<<nb_scan, 512>>>();
    k_fill<<<(EE + 255) / 256, 256>>>(src, dst);

    k_gemm1<<<NN / 32, 256>>>(x, W1);               // 3125 blocks (exact)
    k_agg1<<<(NN * 32 + 255) / 256, 256>>>();       // 12500 blocks
    k_gemm2<<<(NN + 63) / 64, 256>>>(b1, W2);       // 1563 blocks
    k_agg2<<<(NN * 32 + 255) / 256, 256>>>(b2);     // 12500 blocks
    k_decode<<<(2 * EPP * 32 + 255) / 256, 256>>>(pos, neg, out);
}

// round 2
// speedup vs baseline: 1.2027x; 1.2027x over previous
#include <cuda_runtime.h>
#include <cstdint>

#define NN 100000
#define EE 1600000
#define EPP 200000

// ---------------- scratch (static device globals; no allocation) ------------
__device__ int   g_deg[NN];
__device__ int   g_off[NN + 1];
__device__ int   g_cur[NN];
__device__ int   g_adj[EE];
__device__ float g_dinv[NN];
__device__ float g_hs1[(size_t)NN * 128];  // x@W1 (unscaled)
__device__ float g_a1 [(size_t)NN * 128];  // aggregated layer-1 (pre-bias/relu)
__device__ float g_hs2[(size_t)NN * 64];   // relu(a1+b1)@W2 (unscaled)
__device__ float g_z  [(size_t)NN * 64];   // final embeddings
__device__ int   g_bsum[256];
__device__ int   g_boff[256];
__device__ float g_W1hi[128 * 128], g_W1lo[128 * 128];
__device__ float g_W2hi[128 * 64],  g_W2lo[128 * 64];

// ---------------- tf32 helpers ----------------------------------------------
__device__ __forceinline__ uint32_t f2tf(float x) {
    uint32_t r;
    asm("cvt.rna.tf32.f32 %0, %1;" : "=r"(r) : "f"(x));
    return r;
}

__device__ __forceinline__ void mma8(float* c, const uint32_t* a, uint32_t b0, uint32_t b1) {
    asm("mma.sync.aligned.m16n8k8.row.col.f32.tf32.tf32.f32 "
        "{%0,%1,%2,%3}, {%4,%5,%6,%7}, {%8,%9}, {%0,%1,%2,%3};"
        : "+f"(c[0]), "+f"(c[1]), "+f"(c[2]), "+f"(c[3])
        : "r"(a[0]), "r"(a[1]), "r"(a[2]), "r"(a[3]), "r"(b0), "r"(b1));
}

// ---------------- degree / CSR build ----------------------------------------
__global__ void k_init_deg() {
    int i = blockIdx.x * blockDim.x + threadIdx.x;
    if (i < NN) g_deg[i] = 0;
}

__global__ void k_count(const int* __restrict__ dst) {
    int e = blockIdx.x * blockDim.x + threadIdx.x;
    if (e < EE) atomicAdd(&g_deg[dst[e]], 1);
}

__global__ void k_dinv() {
    int i = blockIdx.x * blockDim.x + threadIdx.x;
    if (i < NN) g_dinv[i] = rsqrtf((float)(g_deg[i] + 1));  // +1 self loop
}

__global__ void k_scan1() {
    __shared__ int s[512];
    int t = threadIdx.x;
    int idx = blockIdx.x * 512 + t;
    int v = (idx < NN) ? g_deg[idx] : 0;
    s[t] = v;
    __syncthreads();
#pragma unroll
    for (int o = 1; o < 512; o <<= 1) {
        int x = (t >= o) ? s[t - o] : 0;
        __syncthreads();
        s[t] += x;
        __syncthreads();
    }
    if (idx < NN) g_off[idx] = s[t] - v;
    if (t == 511) g_bsum[blockIdx.x] = s[511];
}

__global__ void k_scan2(int nb) {
    __shared__ int s[256];
    int t = threadIdx.x;
    int v = (t < nb) ? g_bsum[t] : 0;
    s[t] = v;
    __syncthreads();
#pragma unroll
    for (int o = 1; o < 256; o <<= 1) {
        int x = (t >= o) ? s[t - o] : 0;
        __syncthreads();
        s[t] += x;
        __syncthreads();
    }
    if (t < nb) g_boff[t] = s[t] - v;
}

__global__ void k_scan3() {
    int t = threadIdx.x;
    int idx = blockIdx.x * 512 + t;
    if (idx < NN) {
        int val = g_off[idx] + g_boff[blockIdx.x];
        g_off[idx] = val;
        g_cur[idx] = val;
        if (idx == 0) g_off[NN] = EE;
    }
}

__global__ void k_fill(const int* __restrict__ src, const int* __restrict__ dst) {
    int e = blockIdx.x * blockDim.x + threadIdx.x;
    if (e < EE) {
        int d = dst[e];
        int p = atomicAdd(&g_cur[d], 1);
        g_adj[p] = src[e];
    }
}

// ---------------- weight hi/lo split ----------------------------------------
__global__ void k_wprep(const float* __restrict__ W1, const float* __restrict__ W2) {
    int i = blockIdx.x * blockDim.x + threadIdx.x;
    if (i < 128 * 128) {
        float v = W1[i];
        uint32_t h = f2tf(v);
        g_W1hi[i] = __uint_as_float(h);
        g_W1lo[i] = __uint_as_float(f2tf(v - __uint_as_float(h)));
    } else if (i < 128 * 128 + 128 * 64) {
        int j = i - 128 * 128;
        float v = W2[j];
        uint32_t h = f2tf(v);
        g_W2hi[j] = __uint_as_float(h);
        g_W2lo[j] = __uint_as_float(f2tf(v - __uint_as_float(h)));
    }
}

// ---------------- tensor-core GEMM (3xTF32) ----------------------------------
// LAYER 1: hs1[NN,128] = x @ W1          (MT=128, NOUT=128)
// LAYER 2: hs2[NN,64]  = relu(a1+b1)@W2  (MT=256, NOUT=64)
// block = 256 threads = 8 warps, warp tile 32x64, K=128 in 8 chunks of 16.
template<int LAYER>
__global__ __launch_bounds__(256) void k_tc(const float* __restrict__ Xsrc,
                                            const float* __restrict__ bias) {
    constexpr int MT   = (LAYER == 1) ? 128 : 256;
    constexpr int NOUT = (LAYER == 1) ? 128 : 64;
    constexpr int NP   = NOUT + 4;

    const float* Whi = (LAYER == 1) ? g_W1hi : g_W2hi;
    const float* Wlo = (LAYER == 1) ? g_W1lo : g_W2lo;
    const float* Xp  = (LAYER == 1) ? Xsrc : (const float*)g_a1;
    float*       Out = (LAYER == 1) ? g_hs1 : g_hs2;

    __shared__ float Xs[MT * 20];     // 16 cols + pad 4
    __shared__ float Bh[16 * NP];
    __shared__ float Bl[16 * NP];

    const int tid  = threadIdx.x;
    const int lane = tid & 31;
    const int wid  = tid >> 5;
    const int g    = lane >> 2;
    const int t4   = lane & 3;
    const int row0 = blockIdx.x * MT;
    const int warpM = (LAYER == 1) ? (wid >> 1) * 32 : wid * 32;
    const int n0    = (LAYER == 1) ? (wid & 1) * 64 : 0;

    float acc[2][8][4];
#pragma unroll
    for (int mi = 0; mi < 2; mi++)
#pragma unroll
        for (int ni = 0; ni < 8; ni++)
#pragma unroll
            for (int q = 0; q < 4; q++) acc[mi][ni][q] = 0.f;

#pragma unroll 1
    for (int kc = 0; kc < 8; kc++) {
        const int kbase = kc * 16;
        // load X chunk [MT x 16] with optional bias+relu
#pragma unroll
        for (int j = 0; j < MT / 64; j++) {
            int idx = tid + 256 * j;
            int r = idx >> 2, c4 = idx & 3;
            int gr = row0 + r;
            float4 v = {0.f, 0.f, 0.f, 0.f};
            if (gr < NN) {
                v = ((const float4*)(Xp + (size_t)gr * 128 + kbase))[c4];
                if (LAYER == 2) {
                    float4 bb = ((const float4*)(bias + kbase))[c4];
                    v.x = fmaxf(v.x + bb.x, 0.f);
                    v.y = fmaxf(v.y + bb.y, 0.f);
                    v.z = fmaxf(v.z + bb.z, 0.f);
                    v.w = fmaxf(v.w + bb.w, 0.f);
                }
            }
            *((float4*)(Xs + r * 20 + c4 * 4)) = v;
        }
        // load W chunk [16 x NOUT] hi+lo
#pragma unroll
        for (int j = 0; j < (16 * NOUT) / 1024; j++) {
            int idx = tid + 256 * j;
            int kk = idx / (NOUT / 4), c4 = idx % (NOUT / 4);
            float4 vh = ((const float4*)(Whi + (size_t)(kbase + kk) * NOUT))[c4];
            float4 vl = ((const float4*)(Wlo + (size_t)(kbase + kk) * NOUT))[c4];
            *((float4*)(Bh + kk * NP + c4 * 4)) = vh;
            *((float4*)(Bl + kk * NP + c4 * 4)) = vl;
        }
        __syncthreads();

#pragma unroll
        for (int ks = 0; ks < 2; ks++) {
            const int k0 = ks * 8;
            uint32_t ah[2][4], al[2][4];
#pragma unroll
            for (int mi = 0; mi < 2; mi++) {
                int rb = warpM + mi * 16;
                float x0 = Xs[(rb + g) * 20 + k0 + t4];
                float x1 = Xs[(rb + g + 8) * 20 + k0 + t4];
                float x2 = Xs[(rb + g) * 20 + k0 + t4 + 4];
                float x3 = Xs[(rb + g + 8) * 20 + k0 + t4 + 4];
                ah[mi][0] = f2tf(x0); al[mi][0] = f2tf(x0 - __uint_as_float(ah[mi][0]));
                ah[mi][1] = f2tf(x1); al[mi][1] = f2tf(x1 - __uint_as_float(ah[mi][1]));
                ah[mi][2] = f2tf(x2); al[mi][2] = f2tf(x2 - __uint_as_float(ah[mi][2]));
                ah[mi][3] = f2tf(x3); al[mi][3] = f2tf(x3 - __uint_as_float(ah[mi][3]));
            }
#pragma unroll
            for (int ni = 0; ni < 8; ni++) {
                int nn = n0 + ni * 8 + g;
                uint32_t bh0 = __float_as_uint(Bh[(k0 + t4) * NP + nn]);
                uint32_t bh1 = __float_as_uint(Bh[(k0 + t4 + 4) * NP + nn]);
                uint32_t bl0 = __float_as_uint(Bl[(k0 + t4) * NP + nn]);
                uint32_t bl1 = __float_as_uint(Bl[(k0 + t4 + 4) * NP + nn]);
#pragma unroll
                for (int mi = 0; mi < 2; mi++) {
                    mma8(acc[mi][ni], ah[mi], bh0, bh1);  // hi*hi
                    mma8(acc[mi][ni], al[mi], bh0, bh1);  // lo*hi
                    mma8(acc[mi][ni], ah[mi], bl0, bl1);  // hi*lo
                }
            }
        }
        __syncthreads();
    }

    // epilogue (no scaling; dinv applied in aggregation)
#pragma unroll
    for (int mi = 0; mi < 2; mi++) {
#pragma unroll
        for (int ni = 0; ni < 8; ni++) {
            int r  = row0 + warpM + mi * 16 + g;
            int cc = n0 + ni * 8 + 2 * t4;
            if (r < NN) {
                float2 o = {acc[mi][ni][0], acc[mi][ni][1]};
                *((float2*)(Out + (size_t)r * NOUT + cc)) = o;
            }
            if (r + 8 < NN) {
                float2 o = {acc[mi][ni][2], acc[mi][ni][3]};
                *((float2*)(Out + (size_t)(r + 8) * NOUT + cc)) = o;
            }
        }
    }
}

// ---------------- AGG 1: a1[d] = dinv[d]*(hs1[d]*dinv[d] + sum hs1[s]*dinv[s])
__global__ void k_agg1() {
    int gw = (blockIdx.x * blockDim.x + threadIdx.x) >> 5;
    if (gw >= NN) return;
    int lane = threadIdx.x & 31;
    int o0 = g_off[gw], o1 = g_off[gw + 1];
    const float4* base = (const float4*)g_hs1;
    float dd = g_dinv[gw];
    float4 acc = base[(size_t)gw * 32 + lane];
    acc.x *= dd; acc.y *= dd; acc.z *= dd; acc.w *= dd;
    for (int i = o0; i < o1; i++) {
        int s = g_adj[i];
        float ds = g_dinv[s];
        float4 v = base[(size_t)s * 32 + lane];
        acc.x += v.x * ds; acc.y += v.y * ds; acc.z += v.z * ds; acc.w += v.w * ds;
    }
    acc.x *= dd; acc.y *= dd; acc.z *= dd; acc.w *= dd;
    ((float4*)g_a1)[(size_t)gw * 32 + lane] = acc;
}

// ---------------- AGG 2: z[d] = dinv[d]*(hs2[d]*dinv[d] + sum hs2[s]*dinv[s]) + b2
__global__ void k_agg2(const float* __restrict__ b2) {
    int gw = (blockIdx.x * blockDim.x + threadIdx.x) >> 5;
    if (gw >= NN) return;
    int lane = threadIdx.x & 31;
    int o0 = g_off[gw], o1 = g_off[gw + 1];
    const float2* base = (const float2*)g_hs2;
    float dd = g_dinv[gw];
    float2 acc = base[(size_t)gw * 32 + lane];
    acc.x *= dd; acc.y *= dd;
    for (int i = o0; i < o1; i++) {
        int s = g_adj[i];
        float ds = g_dinv[s];
        float2 v = base[(size_t)s * 32 + lane];
        acc.x += v.x * ds; acc.y += v.y * ds;
    }
    float2 b = ((const float2*)b2)[lane];
    acc.x = acc.x * dd + b.x;
    acc.y = acc.y * dd + b.y;
    ((float2*)g_z)[(size_t)gw * 32 + lane] = acc;
}

// ---------------- decode ------------------------------------------------------
__global__ void k_decode(const int* __restrict__ pos, const int* __restrict__ neg,
                         float* __restrict__ out) {
    int gw = (blockIdx.x * blockDim.x + threadIdx.x) >> 5;
    if (gw >= 2 * EPP) return;
    int lane = threadIdx.x & 31;
    int a, b;
    if (gw < EPP) { a = pos[gw];        b = pos[EPP + gw]; }
    else          { int j = gw - EPP; a = neg[j]; b = neg[EPP + j]; }
    const float2* Z = (const float2*)g_z;
    float2 za = Z[(size_t)a * 32 + lane];
    float2 zb = Z[(size_t)b * 32 + lane];
    float p = za.x * zb.x + za.y * zb.y;
#pragma unroll
    for (int o = 16; o > 0; o >>= 1) p += __shfl_xor_sync(0xFFFFFFFFu, p, o);
    if (lane == 0) out[gw] = p;
}

// ---------------- launch ------------------------------------------------------
extern "C" void kernel_launch(void* const* d_in, const int* in_sizes, int n_in,
                              void* d_out, int out_size) {
    const float* x   = (const float*)d_in[0];
    const int*   ei  = (const int*)  d_in[1];
    const int*   pos = (const int*)  d_in[2];
    const int*   neg = (const int*)  d_in[3];
    const float* W1  = (const float*)d_in[4];
    const float* b1  = (const float*)d_in[5];
    const float* W2  = (const float*)d_in[6];
    const float* b2  = (const float*)d_in[7];
    float* out = (float*)d_out;

    const int* src = ei;
    const int* dst = ei + EE;
    const int nb_scan = (NN + 511) / 512;  // 196

    static cudaStream_t s2 = nullptr;
    static cudaEvent_t ev0 = nullptr, ev1 = nullptr;
    if (!s2) {
        cudaStreamCreateWithFlags(&s2, cudaStreamNonBlocking);
        cudaEventCreateWithFlags(&ev0, cudaEventDisableTiming);
        cudaEventCreateWithFlags(&ev1, cudaEventDisableTiming);
    }

    // fork: gemm1 (+ weight prep) has no CSR dependency
    cudaEventRecord(ev0, 0);
    cudaStreamWaitEvent(s2, ev0, 0);
    k_wprep<<<(128 * 128 + 128 * 64 + 255) / 256, 256, 0, s2>>>(W1, W2);
    k_tc<1><<<(NN + 127) / 128, 256, 0, s2>>>(x, nullptr);
    cudaEventRecord(ev1, s2);

    // main stream: CSR build
    k_init_deg<<<(NN + 255) / 256, 256>>>();
    k_count<<<(EE + 255) / 256, 256>>>(dst);
    k_dinv<<<(NN + 255) / 256, 256>>>();
    k_scan1<<<nb_scan, 512>>>();
    k_scan2<<<1, 256>>>(nb_scan);
    k_scan3<<<nb_scan, 512>>>();
    k_fill<<<(EE + 255) / 256, 256>>>(src, dst);

    // join
    cudaStreamWaitEvent(0, ev1, 0);

    k_agg1<<<(NN * 32 + 255) / 256, 256>>>();
    k_tc<2><<<(NN + 255) / 256, 256>>>(nullptr, b1);
    k_agg2<<<(NN * 32 + 255) / 256, 256>>>(b2);
    k_decode<<<(2 * EPP * 32 + 255) / 256, 256>>>(pos, neg, out);
}

// round 3
// speedup vs baseline: 1.2548x; 1.0433x over previous
#include <cuda_runtime.h>
#include <cuda_fp16.h>
#include <cstdint>

#define NN 100000
#define EE 1600000
#define EPP 200000

// ---------------- scratch (static device globals; no allocation) ------------
__device__ int    g_deg[NN];
__device__ int    g_off[NN + 1];
__device__ int    g_cur[NN];
__device__ int    g_adj[EE];
__device__ float  g_dinv[NN];
__device__ __half g_hs1[(size_t)NN * 128];  // x@W1 (unscaled, fp16)
__device__ float  g_a1 [(size_t)NN * 128];  // aggregated layer-1 (pre-bias/relu)
__device__ __half g_hs2[(size_t)NN * 64];   // relu(a1+b1)@W2 (unscaled, fp16)
__device__ float  g_z  [(size_t)NN * 64];   // final embeddings (fp32)
__device__ int    g_bsum[256];
__device__ int    g_boff[256];
__device__ float  g_W1hi[128 * 128], g_W1lo[128 * 128];
__device__ float  g_W2hi[128 * 64],  g_W2lo[128 * 64];

// ---------------- tf32 helpers ----------------------------------------------
__device__ __forceinline__ uint32_t f2tf(float x) {
    uint32_t r;
    asm("cvt.rna.tf32.f32 %0, %1;" : "=r"(r) : "f"(x));
    return r;
}

__device__ __forceinline__ void mma8(float* c, const uint32_t* a, uint32_t b0, uint32_t b1) {
    asm("mma.sync.aligned.m16n8k8.row.col.f32.tf32.tf32.f32 "
        "{%0,%1,%2,%3}, {%4,%5,%6,%7}, {%8,%9}, {%0,%1,%2,%3};"
        : "+f"(c[0]), "+f"(c[1]), "+f"(c[2]), "+f"(c[3])
        : "r"(a[0]), "r"(a[1]), "r"(a[2]), "r"(a[3]), "r"(b0), "r"(b1));
}

// ---------------- degree / CSR build ----------------------------------------
__global__ void k_init_deg() {
    int i = blockIdx.x * blockDim.x + threadIdx.x;
    if (i < NN) g_deg[i] = 0;
}

__global__ void k_count(const int* __restrict__ dst) {
    int e = blockIdx.x * blockDim.x + threadIdx.x;
    if (e < EE) atomicAdd(&g_deg[dst[e]], 1);
}

__global__ void k_dinv() {
    int i = blockIdx.x * blockDim.x + threadIdx.x;
    if (i < NN) g_dinv[i] = rsqrtf((float)(g_deg[i] + 1));  // +1 self loop
}

__global__ void k_scan1() {
    __shared__ int s[512];
    int t = threadIdx.x;
    int idx = blockIdx.x * 512 + t;
    int v = (idx < NN) ? g_deg[idx] : 0;
    s[t] = v;
    __syncthreads();
#pragma unroll
    for (int o = 1; o < 512; o <<= 1) {
        int x = (t >= o) ? s[t - o] : 0;
        __syncthreads();
        s[t] += x;
        __syncthreads();
    }
    if (idx < NN) g_off[idx] = s[t] - v;
    if (t == 511) g_bsum[blockIdx.x] = s[511];
}

__global__ void k_scan2(int nb) {
    __shared__ int s[256];
    int t = threadIdx.x;
    int v = (t < nb) ? g_bsum[t] : 0;
    s[t] = v;
    __syncthreads();
#pragma unroll
    for (int o = 1; o < 256; o <<= 1) {
        int x = (t >= o) ? s[t - o] : 0;
        __syncthreads();
        s[t] += x;
        __syncthreads();
    }
    if (t < nb) g_boff[t] = s[t] - v;
}

__global__ void k_scan3() {
    int t = threadIdx.x;
    int idx = blockIdx.x * 512 + t;
    if (idx < NN) {
        int val = g_off[idx] + g_boff[blockIdx.x];
        g_off[idx] = val;
        g_cur[idx] = val;
        if (idx == 0) g_off[NN] = EE;
    }
}

__global__ void k_fill(const int* __restrict__ src, const int* __restrict__ dst) {
    int e = blockIdx.x * blockDim.x + threadIdx.x;
    if (e < EE) {
        int d = dst[e];
        int p = atomicAdd(&g_cur[d], 1);
        g_adj[p] = src[e];
    }
}

// ---------------- weight hi/lo split ----------------------------------------
__global__ void k_wprep(const float* __restrict__ W1, const float* __restrict__ W2) {
    int i = blockIdx.x * blockDim.x + threadIdx.x;
    if (i < 128 * 128) {
        float v = W1[i];
        uint32_t h = f2tf(v);
        g_W1hi[i] = __uint_as_float(h);
        g_W1lo[i] = __uint_as_float(f2tf(v - __uint_as_float(h)));
    } else if (i < 128 * 128 + 128 * 64) {
        int j = i - 128 * 128;
        float v = W2[j];
        uint32_t h = f2tf(v);
        g_W2hi[j] = __uint_as_float(h);
        g_W2lo[j] = __uint_as_float(f2tf(v - __uint_as_float(h)));
    }
}

// ---------------- tensor-core GEMM (3xTF32), fp16 output ---------------------
// LAYER 1: hs1[NN,128] = x @ W1          (MT=128, NOUT=128)
// LAYER 2: hs2[NN,64]  = relu(a1+b1)@W2  (MT=256, NOUT=64)
template<int LAYER>
__global__ __launch_bounds__(256) void k_tc(const float* __restrict__ Xsrc,
                                            const float* __restrict__ bias) {
    constexpr int MT   = (LAYER == 1) ? 128 : 256;
    constexpr int NOUT = (LAYER == 1) ? 128 : 64;
    constexpr int NP   = NOUT + 4;

    const float* Whi = (LAYER == 1) ? g_W1hi : g_W2hi;
    const float* Wlo = (LAYER == 1) ? g_W1lo : g_W2lo;
    const float* Xp  = (LAYER == 1) ? Xsrc : (const float*)g_a1;
    __half*      Out = (LAYER == 1) ? g_hs1 : g_hs2;

    __shared__ float Xs[MT * 20];     // 16 cols + pad 4
    __shared__ float Bh[16 * NP];
    __shared__ float Bl[16 * NP];

    const int tid  = threadIdx.x;
    const int lane = tid & 31;
    const int wid  = tid >> 5;
    const int g    = lane >> 2;
    const int t4   = lane & 3;
    const int row0 = blockIdx.x * MT;
    const int warpM = (LAYER == 1) ? (wid >> 1) * 32 : wid * 32;
    const int n0    = (LAYER == 1) ? (wid & 1) * 64 : 0;

    float acc[2][8][4];
#pragma unroll
    for (int mi = 0; mi < 2; mi++)
#pragma unroll
        for (int ni = 0; ni < 8; ni++)
#pragma unroll
            for (int q = 0; q < 4; q++) acc[mi][ni][q] = 0.f;

#pragma unroll 1
    for (int kc = 0; kc < 8; kc++) {
        const int kbase = kc * 16;
#pragma unroll
        for (int j = 0; j < MT / 64; j++) {
            int idx = tid + 256 * j;
            int r = idx >> 2, c4 = idx & 3;
            int gr = row0 + r;
            float4 v = {0.f, 0.f, 0.f, 0.f};
            if (gr < NN) {
                v = ((const float4*)(Xp + (size_t)gr * 128 + kbase))[c4];
                if (LAYER == 2) {
                    float4 bb = ((const float4*)(bias + kbase))[c4];
                    v.x = fmaxf(v.x + bb.x, 0.f);
                    v.y = fmaxf(v.y + bb.y, 0.f);
                    v.z = fmaxf(v.z + bb.z, 0.f);
                    v.w = fmaxf(v.w + bb.w, 0.f);
                }
            }
            *((float4*)(Xs + r * 20 + c4 * 4)) = v;
        }
#pragma unroll
        for (int j = 0; j < (16 * NOUT) / 1024; j++) {
            int idx = tid + 256 * j;
            int kk = idx / (NOUT / 4), c4 = idx % (NOUT / 4);
            float4 vh = ((const float4*)(Whi + (size_t)(kbase + kk) * NOUT))[c4];
            float4 vl = ((const float4*)(Wlo + (size_t)(kbase + kk) * NOUT))[c4];
            *((float4*)(Bh + kk * NP + c4 * 4)) = vh;
            *((float4*)(Bl + kk * NP + c4 * 4)) = vl;
        }
        __syncthreads();

#pragma unroll
        for (int ks = 0; ks < 2; ks++) {
            const int k0 = ks * 8;
            uint32_t ah[2][4], al[2][4];
#pragma unroll
            for (int mi = 0; mi < 2; mi++) {
                int rb = warpM + mi * 16;
                float x0 = Xs[(rb + g) * 20 + k0 + t4];
                float x1 = Xs[(rb + g + 8) * 20 + k0 + t4];
                float x2 = Xs[(rb + g) * 20 + k0 + t4 + 4];
                float x3 = Xs[(rb + g + 8) * 20 + k0 + t4 + 4];
                ah[mi][0] = f2tf(x0); al[mi][0] = f2tf(x0 - __uint_as_float(ah[mi][0]));
                ah[mi][1] = f2tf(x1); al[mi][1] = f2tf(x1 - __uint_as_float(ah[mi][1]));
                ah[mi][2] = f2tf(x2); al[mi][2] = f2tf(x2 - __uint_as_float(ah[mi][2]));
                ah[mi][3] = f2tf(x3); al[mi][3] = f2tf(x3 - __uint_as_float(ah[mi][3]));
            }
#pragma unroll
            for (int ni = 0; ni < 8; ni++) {
                int nn = n0 + ni * 8 + g;
                uint32_t bh0 = __float_as_uint(Bh[(k0 + t4) * NP + nn]);
                uint32_t bh1 = __float_as_uint(Bh[(k0 + t4 + 4) * NP + nn]);
                uint32_t bl0 = __float_as_uint(Bl[(k0 + t4) * NP + nn]);
                uint32_t bl1 = __float_as_uint(Bl[(k0 + t4 + 4) * NP + nn]);
#pragma unroll
                for (int mi = 0; mi < 2; mi++) {
                    mma8(acc[mi][ni], ah[mi], bh0, bh1);  // hi*hi
                    mma8(acc[mi][ni], al[mi], bh0, bh1);  // lo*hi
                    mma8(acc[mi][ni], ah[mi], bl0, bl1);  // hi*lo
                }
            }
        }
        __syncthreads();
    }

    // epilogue: fp16 output (no scaling; dinv applied in aggregation)
#pragma unroll
    for (int mi = 0; mi < 2; mi++) {
#pragma unroll
        for (int ni = 0; ni < 8; ni++) {
            int r  = row0 + warpM + mi * 16 + g;
            int cc = n0 + ni * 8 + 2 * t4;
            if (r < NN) {
                __half2 o = __floats2half2_rn(acc[mi][ni][0], acc[mi][ni][1]);
                *((__half2*)(Out + (size_t)r * NOUT + cc)) = o;
            }
            if (r + 8 < NN) {
                __half2 o = __floats2half2_rn(acc[mi][ni][2], acc[mi][ni][3]);
                *((__half2*)(Out + (size_t)(r + 8) * NOUT + cc)) = o;
            }
        }
    }
}

// ---------------- AGG 1: a1[d] = dinv[d]*(hs1[d]*dinv[d] + sum hs1[s]*dinv[s])
// warp per node; lane covers dims [4*lane .. 4*lane+3] (two half2 = 8B load)
__global__ void k_agg1() {
    int gw = (blockIdx.x * blockDim.x + threadIdx.x) >> 5;
    if (gw >= NN) return;
    int lane = threadIdx.x & 31;
    int o0 = g_off[gw], o1 = g_off[gw + 1];
    const uint2* base = (const uint2*)g_hs1;   // 32 uint2 per row
    float dd = g_dinv[gw];

    uint2 sv = base[(size_t)gw * 32 + lane];
    float2 p0 = __half22float2(*reinterpret_cast<const __half2*>(&sv.x));
    float2 p1 = __half22float2(*reinterpret_cast<const __half2*>(&sv.y));
    float a0 = p0.x * dd, a1 = p0.y * dd, a2 = p1.x * dd, a3 = p1.y * dd;

    for (int i = o0; i < o1; i++) {
        int s = g_adj[i];
        float ds = g_dinv[s];
        uint2 v = base[(size_t)s * 32 + lane];
        float2 q0 = __half22float2(*reinterpret_cast<const __half2*>(&v.x));
        float2 q1 = __half22float2(*reinterpret_cast<const __half2*>(&v.y));
        a0 += q0.x * ds; a1 += q0.y * ds; a2 += q1.x * ds; a3 += q1.y * ds;
    }
    float4 o = {a0 * dd, a1 * dd, a2 * dd, a3 * dd};
    ((float4*)g_a1)[(size_t)gw * 32 + lane] = o;
}

// ---------------- AGG 2: z[d] = dinv[d]*(hs2[d]*dinv[d] + sum hs2[s]*dinv[s]) + b2
// warp per node; lane covers dims [2*lane, 2*lane+1] (one half2 = 4B load)
__global__ void k_agg2(const float* __restrict__ b2) {
    int gw = (blockIdx.x * blockDim.x + threadIdx.x) >> 5;
    if (gw >= NN) return;
    int lane = threadIdx.x & 31;
    int o0 = g_off[gw], o1 = g_off[gw + 1];
    const __half2* base = (const __half2*)g_hs2;  // 32 half2 per row
    float dd = g_dinv[gw];

    float2 p = __half22float2(base[(size_t)gw * 32 + lane]);
    float a0 = p.x * dd, a1 = p.y * dd;

    for (int i = o0; i < o1; i++) {
        int s = g_adj[i];
        float ds = g_dinv[s];
        float2 v = __half22float2(base[(size_t)s * 32 + lane]);
        a0 += v.x * ds; a1 += v.y * ds;
    }
    float2 b = ((const float2*)b2)[lane];
    float2 o = {a0 * dd + b.x, a1 * dd + b.y};
    ((float2*)g_z)[(size_t)gw * 32 + lane] = o;
}

// ---------------- decode ------------------------------------------------------
__global__ void k_decode(const int* __restrict__ pos, const int* __restrict__ neg,
                         float* __restrict__ out) {
    int gw = (blockIdx.x * blockDim.x + threadIdx.x) >> 5;
    if (gw >= 2 * EPP) return;
    int lane = threadIdx.x & 31;
    int a, b;
    if (gw < EPP) { a = pos[gw];        b = pos[EPP + gw]; }
    else          { int j = gw - EPP; a = neg[j]; b = neg[EPP + j]; }
    const float2* Z = (const float2*)g_z;
    float2 za = Z[(size_t)a * 32 + lane];
    float2 zb = Z[(size_t)b * 32 + lane];
    float p = za.x * zb.x + za.y * zb.y;
#pragma unroll
    for (int o = 16; o > 0; o >>= 1) p += __shfl_xor_sync(0xFFFFFFFFu, p, o);
    if (lane == 0) out[gw] = p;
}

// ---------------- launch ------------------------------------------------------
extern "C" void kernel_launch(void* const* d_in, const int* in_sizes, int n_in,
                              void* d_out, int out_size) {
    const float* x   = (const float*)d_in[0];
    const int*   ei  = (const int*)  d_in[1];
    const int*   pos = (const int*)  d_in[2];
    const int*   neg = (const int*)  d_in[3];
    const float* W1  = (const float*)d_in[4];
    const float* b1  = (const float*)d_in[5];
    const float* W2  = (const float*)d_in[6];
    const float* b2  = (const float*)d_in[7];
    float* out = (float*)d_out;

    const int* src = ei;
    const int* dst = ei + EE;
    const int nb_scan = (NN + 511) / 512;  // 196

    static cudaStream_t s2 = nullptr;
    static cudaEvent_t ev0 = nullptr, ev1 = nullptr;
    if (!s2) {
        cudaStreamCreateWithFlags(&s2, cudaStreamNonBlocking);
        cudaEventCreateWithFlags(&ev0, cudaEventDisableTiming);
        cudaEventCreateWithFlags(&ev1, cudaEventDisableTiming);
    }

    // fork: gemm1 (+ weight prep) has no CSR dependency
    cudaEventRecord(ev0, 0);
    cudaStreamWaitEvent(s2, ev0, 0);
    k_wprep<<<(128 * 128 + 128 * 64 + 255) / 256, 256, 0, s2>>>(W1, W2);
    k_tc<1><<<(NN + 127) / 128, 256, 0, s2>>>(x, nullptr);
    cudaEventRecord(ev1, s2);

    // main stream: CSR build
    k_init_deg<<<(NN + 255) / 256, 256>>>();
    k_count<<<(EE + 255) / 256, 256>>>(dst);
    k_dinv<<<(NN + 255) / 256, 256>>>();
    k_scan1<<<nb_scan, 512>>>();
    k_scan2<<<1, 256>>>(nb_scan);
    k_scan3<<<nb_scan, 512>>>();
    k_fill<<<(EE + 255) / 256, 256>>>(src, dst);

    // join
    cudaStreamWaitEvent(0, ev1, 0);

    k_agg1<<<(NN * 32 + 255) / 256, 256>>>();
    k_tc<2><<<(NN + 255) / 256, 256>>>(nullptr, b1);
    k_agg2<<<(NN * 32 + 255) / 256, 256>>>(b2);
    k_decode<<<(2 * EPP * 32 + 255) / 256, 256>>>(pos, neg, out);
}